// round 6
// baseline (speedup 1.0000x reference)
#include <cuda_runtime.h>
#include <math.h>

#define E_EDGES 16384
#define NNODES  10000
#define D       128

// Scratch (device globals: no allocation allowed)
__device__ float g_h[E_EDGES * D];     // relu(edge_attr @ w1 + b1)
__device__ float g_seg[NNODES * D];    // scatter-sum of messages
__device__ float g_cnt[NNODES];        // per-destination edge counts

__device__ __forceinline__ int clamp_node(int v) {
    v = v < 0 ? 0 : v;
    return v >= NNODES ? NNODES - 1 : v;
}

// ---------------------------------------------------------------------------
// K0: zero accumulators
// ---------------------------------------------------------------------------
__global__ void zero_kernel() {
    int i = blockIdx.x * blockDim.x + threadIdx.x;
    if (i < NNODES * D) g_seg[i] = 0.0f;
    if (i < NNODES)     g_cnt[i] = 0.0f;
}

// ---------------------------------------------------------------------------
// K0b: per-destination edge counts  (edge_index is int32: jax silently
// downcasts the requested int64 unless x64 mode is on)
// ---------------------------------------------------------------------------
__global__ void count_kernel(const int* __restrict__ ei) {
    int e = blockIdx.x * blockDim.x + threadIdx.x;
    if (e < E_EDGES) {
        int d = clamp_node(ei[E_EDGES + e]);
        atomicAdd(&g_cnt[d], 1.0f);
    }
}

// ---------------------------------------------------------------------------
// K1: h = relu(edge_attr @ w1 + b1). 8 edges per 128-thread block.
// ---------------------------------------------------------------------------
__global__ __launch_bounds__(128) void edge_mlp1_kernel(
    const float* __restrict__ ea,
    const float* __restrict__ w1,
    const float* __restrict__ b1)
{
    __shared__ float sa[8][D];
    const int o  = threadIdx.x;
    const int e0 = blockIdx.x * 8;

    for (int t = threadIdx.x; t < 8 * D; t += 128)
        sa[t >> 7][t & 127] = ea[e0 * D + t];
    __syncthreads();

    float acc[8];
#pragma unroll
    for (int r = 0; r < 8; r++) acc[r] = 0.0f;

    for (int i = 0; i < D; i++) {
        float w = w1[i * D + o];
#pragma unroll
        for (int r = 0; r < 8; r++) acc[r] += sa[r][i] * w;
    }
    float bb = b1[o];
#pragma unroll
    for (int r = 0; r < 8; r++)
        g_h[(size_t)(e0 + r) * D + o] = fmaxf(acc[r] + bb, 0.0f);
}

// ---------------------------------------------------------------------------
// K2: fused bilinear message + scatter-add.
//   msg[e,o] = sum_k h[e,k] * sum_i x[src[e],i] * w2[k, i*D+o]
//            + sum_i x[src[e],i] * b2[i*D+o]
// Tiled as a GEMM with on-the-fly A = h[e,k]*x[e,i].
// BM=32 edges per 256-thread block; thread tile 2 edges x 8 outputs.
// ---------------------------------------------------------------------------
#define BM 32
#define BK 16

__global__ __launch_bounds__(256) void bilinear_kernel(
    const float* __restrict__ x,
    const int* __restrict__ ei,
    const float* __restrict__ w2,
    const float* __restrict__ b2)
{
    __shared__ float  Xs[BM][D + 1];
    __shared__ float  Hs[BM][D + 1];
    __shared__ float4 Ws[BK * 32];       // BK rows x 128 floats
    __shared__ int    ssrc[BM], sdst[BM];

    const int tid = threadIdx.x;
    const int e0  = blockIdx.x * BM;

    if (tid < BM) {
        ssrc[tid] = clamp_node(ei[e0 + tid]);
        sdst[tid] = clamp_node(ei[E_EDGES + e0 + tid]);
    }
    __syncthreads();

    // Load gathered x rows + h rows (coalesced float4 reads, scalar smem stores)
    for (int f = tid; f < BM * 32; f += 256) {
        int e = f >> 5, iv = f & 31;
        float4 v = ((const float4*)(x + (size_t)ssrc[e] * D))[iv];
        Xs[e][iv * 4 + 0] = v.x; Xs[e][iv * 4 + 1] = v.y;
        Xs[e][iv * 4 + 2] = v.z; Xs[e][iv * 4 + 3] = v.w;
        float4 hv = ((const float4*)(g_h + (size_t)(e0 + e) * D))[iv];
        Hs[e][iv * 4 + 0] = hv.x; Hs[e][iv * 4 + 1] = hv.y;
        Hs[e][iv * 4 + 2] = hv.z; Hs[e][iv * 4 + 3] = hv.w;
    }
    __syncthreads();

    const int tx = tid & 15;       // output group: o0 = tx*8
    const int ty = tid >> 4;       // edge group:  eb = ty*2
    const int o0 = tx * 8;
    const int eb = ty * 2;

    float acc[2][8];
#pragma unroll
    for (int c = 0; c < 2; c++)
#pragma unroll
        for (int n = 0; n < 8; n++) acc[c][n] = 0.0f;

    // k = 0..127 uses h[e,k] and w2 row k; k = 128 is the b2 term with h = 1.
    for (int k = 0; k <= D; k++) {
        const float h0 = (k < D) ? Hs[eb][k]     : 1.0f;
        const float h1 = (k < D) ? Hs[eb + 1][k] : 1.0f;
        const float* wrow = (k < D) ? (w2 + (size_t)k * (D * D)) : b2;

        for (int ii = 0; ii < D; ii += BK) {
            __syncthreads();
            const float4* wr = (const float4*)(wrow + ii * D);
            Ws[tid]       = wr[tid];
            Ws[tid + 256] = wr[tid + 256];
            __syncthreads();

#pragma unroll
            for (int j = 0; j < BK; j++) {
                float4 B0 = Ws[j * 32 + tx * 2];
                float4 B1 = Ws[j * 32 + tx * 2 + 1];
                float a0 = h0 * Xs[eb][ii + j];
                float a1 = h1 * Xs[eb + 1][ii + j];

                acc[0][0] += a0 * B0.x; acc[0][1] += a0 * B0.y;
                acc[0][2] += a0 * B0.z; acc[0][3] += a0 * B0.w;
                acc[0][4] += a0 * B1.x; acc[0][5] += a0 * B1.y;
                acc[0][6] += a0 * B1.z; acc[0][7] += a0 * B1.w;

                acc[1][0] += a1 * B0.x; acc[1][1] += a1 * B0.y;
                acc[1][2] += a1 * B0.z; acc[1][3] += a1 * B0.w;
                acc[1][4] += a1 * B1.x; acc[1][5] += a1 * B1.y;
                acc[1][6] += a1 * B1.z; acc[1][7] += a1 * B1.w;
            }
        }
    }

    // Scatter-add into destination accumulator
#pragma unroll
    for (int c = 0; c < 2; c++) {
        int d = sdst[eb + c];
        float* p = g_seg + (size_t)d * D + o0;
#pragma unroll
        for (int n = 0; n < 8; n++) atomicAdd(p + n, acc[c][n]);
    }
}

// ---------------------------------------------------------------------------
// K3: out = x + gelu(seg/max(cnt,1) + x @ root + bias). 8 nodes per block.
// ---------------------------------------------------------------------------
__global__ __launch_bounds__(128) void out_kernel(
    const float* __restrict__ x,
    const float* __restrict__ root,
    const float* __restrict__ bias,
    float* __restrict__ out)
{
    __shared__ float xsh[8][D];
    const int o  = threadIdx.x;
    const int n0 = blockIdx.x * 8;
    const int nmax = (NNODES - n0 < 8) ? (NNODES - n0) : 8;

    for (int t = threadIdx.x; t < 8 * D; t += 128) {
        int r = t >> 7;
        xsh[r][t & 127] = (r < nmax) ? x[(size_t)(n0 + r) * D + (t & 127)] : 0.0f;
    }
    __syncthreads();

    float acc[8];
#pragma unroll
    for (int r = 0; r < 8; r++) acc[r] = 0.0f;

    for (int i = 0; i < D; i++) {
        float w = root[i * D + o];
#pragma unroll
        for (int r = 0; r < 8; r++) acc[r] += xsh[r][i] * w;
    }

    float bb = bias[o];
    for (int r = 0; r < nmax; r++) {
        int n = n0 + r;
        float cnt  = g_cnt[n];
        float aggr = g_seg[(size_t)n * D + o] / fmaxf(cnt, 1.0f);
        float v = aggr + acc[r] + bb;
        float g = 0.5f * v * (1.0f + erff(v * 0.70710678118654752f));
        out[(size_t)n * D + o] = xsh[r][o] + g;
    }
}

// ---------------------------------------------------------------------------
// Launch
// ---------------------------------------------------------------------------
extern "C" void kernel_launch(void* const* d_in, const int* in_sizes, int n_in,
                              void* d_out, int out_size)
{
    const float* x    = (const float*)d_in[0];
    const int*   ei   = (const int*)d_in[1];     // int32 (jax downcasts int64)
    const float* ea   = (const float*)d_in[2];
    const float* w1   = (const float*)d_in[3];
    const float* b1   = (const float*)d_in[4];
    const float* w2   = (const float*)d_in[5];
    const float* b2   = (const float*)d_in[6];
    const float* root = (const float*)d_in[7];
    const float* bias = (const float*)d_in[8];
    float*       out  = (float*)d_out;

    zero_kernel<<<(NNODES * D + 255) / 256, 256>>>();
    count_kernel<<<(E_EDGES + 255) / 256, 256>>>(ei);
    edge_mlp1_kernel<<<E_EDGES / 8, 128>>>(ea, w1, b1);
    bilinear_kernel<<<E_EDGES / BM, 256>>>(x, ei, w2, b2);
    out_kernel<<<(NNODES + 7) / 8, 128>>>(x, root, bias, out);
}

// round 7
// speedup vs baseline: 2.9847x; 2.9847x over previous
#include <cuda_runtime.h>
#include <math.h>

#define E_EDGES 16384
#define NNODES  10000
#define D       128

#define BM      128          // edges per block (K2)
#define HST     132          // padded row stride for HsT (16B-aligned: 132*4=528)

// Scratch (device globals: no allocation allowed)
__device__ float g_h[E_EDGES * D];     // relu(edge_attr @ w1 + b1)
__device__ float g_seg[NNODES * D];    // scatter-sum of messages
__device__ float g_cnt[NNODES];        // per-destination edge counts

__device__ __forceinline__ int clamp_node(int v) {
    v = v < 0 ? 0 : v;
    return v >= NNODES ? NNODES - 1 : v;
}

// ---- packed f32x2 helpers (FFMA2: B300 3-reg FFMA is half-rate; f32x2 restores it) ----
typedef unsigned long long u64t;
__device__ __forceinline__ u64t pk2(float lo, float hi) {
    u64t r; asm("mov.b64 %0, {%1,%2};" : "=l"(r) : "f"(lo), "f"(hi)); return r;
}
__device__ __forceinline__ u64t dup2(float v) {
    u64t r; asm("mov.b64 %0, {%1,%1};" : "=l"(r) : "f"(v)); return r;
}
__device__ __forceinline__ u64t mul2(u64t a, u64t b) {
    u64t r; asm("mul.rn.f32x2 %0, %1, %2;" : "=l"(r) : "l"(a), "l"(b)); return r;
}
__device__ __forceinline__ u64t fma2(u64t a, u64t b, u64t c) {
    u64t r; asm("fma.rn.f32x2 %0, %1, %2, %3;" : "=l"(r) : "l"(a), "l"(b), "l"(c)); return r;
}
__device__ __forceinline__ void upk2(u64t v, float& lo, float& hi) {
    asm("mov.b64 {%0,%1}, %2;" : "=f"(lo), "=f"(hi) : "l"(v));
}

// ---------------------------------------------------------------------------
// K0: zero accumulators
// ---------------------------------------------------------------------------
__global__ void zero_kernel() {
    int i = blockIdx.x * blockDim.x + threadIdx.x;
    if (i < NNODES * D) g_seg[i] = 0.0f;
    if (i < NNODES)     g_cnt[i] = 0.0f;
}

// ---------------------------------------------------------------------------
// K0b: per-destination edge counts (edge_index is int32)
// ---------------------------------------------------------------------------
__global__ void count_kernel(const int* __restrict__ ei) {
    int e = blockIdx.x * blockDim.x + threadIdx.x;
    if (e < E_EDGES) {
        int d = clamp_node(ei[E_EDGES + e]);
        atomicAdd(&g_cnt[d], 1.0f);
    }
}

// ---------------------------------------------------------------------------
// K1: h = relu(edge_attr @ w1 + b1). 8 edges per 128-thread block.
// ---------------------------------------------------------------------------
__global__ __launch_bounds__(128) void edge_mlp1_kernel(
    const float* __restrict__ ea,
    const float* __restrict__ w1,
    const float* __restrict__ b1)
{
    __shared__ float sa[8][D];
    const int o  = threadIdx.x;
    const int e0 = blockIdx.x * 8;

    for (int t = threadIdx.x; t < 8 * D; t += 128)
        sa[t >> 7][t & 127] = ea[e0 * D + t];
    __syncthreads();

    float acc[8];
#pragma unroll
    for (int r = 0; r < 8; r++) acc[r] = 0.0f;

    for (int i = 0; i < D; i++) {
        float w = w1[i * D + o];
#pragma unroll
        for (int r = 0; r < 8; r++) acc[r] += sa[r][i] * w;
    }
    float bb = b1[o];
#pragma unroll
    for (int r = 0; r < 8; r++)
        g_h[(size_t)(e0 + r) * D + o] = fmaxf(acc[r] + bb, 0.0f);
}

// ---------------------------------------------------------------------------
// K2 (restructured): msg = sum_i diag(x[:,i]) * (H @ W2_i), + b2 via row 128.
// Block: 128 edges x 128 outputs, 256 threads, thread tile 8 edges x 8 outs.
// Outer loop i: load W2_i (128x128 + b2 row) into smem once (2 barriers/i).
// Inner loop j(=k): a'[e] = HsT[j][e]*x[e,i]; acc += a' (x) Ws[j][:].
// Edge-paired f32x2 accumulators -> 32 FFMA2 + 4 FMUL2 per j per thread.
// ---------------------------------------------------------------------------
__global__ __launch_bounds__(256, 1) void bilinear2_kernel(
    const float* __restrict__ x,
    const int* __restrict__ ei,
    const float* __restrict__ w2,
    const float* __restrict__ b2)
{
    extern __shared__ float sm[];
    float* HsT  = sm;                       // [129][HST]  h transposed; row 128 = 1.0
    float* Ws   = sm + 129 * HST;           // [129][128]  W2_i tile; row 128 = b2 slice
    int*   ssrc = (int*)(Ws + 129 * 128);   // [128]
    int*   sdst = ssrc + BM;                // [128]

    const int tid = threadIdx.x;
    const int tx  = tid & 15;               // output chunks: tx*4 and 64+tx*4
    const int ty  = tid >> 4;               // edges ty*8 .. ty*8+7
    const int e0  = blockIdx.x * BM;

    if (tid < BM) {
        ssrc[tid] = clamp_node(ei[e0 + tid]);
        sdst[tid] = clamp_node(ei[E_EDGES + e0 + tid]);
    }

    // Load h rows for this block's edges, transposed into HsT[k][e].
    for (int t = tid; t < BM * 32; t += 256) {
        int e = t >> 5, kv = t & 31;
        float4 hv = ((const float4*)(g_h + (size_t)(e0 + e) * D))[kv];
        HsT[(kv * 4 + 0) * HST + e] = hv.x;
        HsT[(kv * 4 + 1) * HST + e] = hv.y;
        HsT[(kv * 4 + 2) * HST + e] = hv.z;
        HsT[(kv * 4 + 3) * HST + e] = hv.w;
    }
    for (int e = tid; e < BM; e += 256) HsT[128 * HST + e] = 1.0f;
    __syncthreads();

    // Per-thread source node ids (8 edges)
    int mysrc[8];
#pragma unroll
    for (int r = 0; r < 8; r++) mysrc[r] = ssrc[ty * 8 + r];

    u64t acc[4][8];
#pragma unroll
    for (int p = 0; p < 4; p++)
#pragma unroll
        for (int n = 0; n < 8; n++) acc[p][n] = 0ULL;

    for (int i = 0; i < D; i++) {
        __syncthreads();   // previous tile fully consumed
        // Cooperative load: Ws[k][o] = w2[k][i*128+o], row 128 = b2[i*128+o]
        for (int t = tid; t < 129 * 32; t += 256) {
            int k = t >> 5, o4 = t & 31;
            const float* srcp = (k < 128)
                ? (w2 + (size_t)k * (D * D) + i * D + o4 * 4)
                : (b2 + i * D + o4 * 4);
            *(float4*)(Ws + k * D + o4 * 4) = *(const float4*)srcp;
        }
        // x fragment for this i (L1-resident gathered rows), packed by edge-pair
        float xv[8];
#pragma unroll
        for (int r = 0; r < 8; r++)
            xv[r] = __ldg(x + (size_t)mysrc[r] * D + i);
        u64t x2[4];
#pragma unroll
        for (int p = 0; p < 4; p++) x2[p] = pk2(xv[2 * p], xv[2 * p + 1]);
        __syncthreads();   // tile ready

#pragma unroll 4
        for (int j = 0; j < 129; j++) {
            // h fragment: 8 edges as 4 packed pairs (warp-broadcast, conflict-free)
            ulonglong2 hA = *(const ulonglong2*)(HsT + j * HST + ty * 8);
            ulonglong2 hB = *(const ulonglong2*)(HsT + j * HST + ty * 8 + 4);
            u64t a2[4];
            a2[0] = mul2(hA.x, x2[0]);
            a2[1] = mul2(hA.y, x2[1]);
            a2[2] = mul2(hB.x, x2[2]);
            a2[3] = mul2(hB.y, x2[3]);

            // b fragment: lane-contiguous, conflict-free
            float4 bA = *(const float4*)(Ws + j * D + tx * 4);
            float4 bB = *(const float4*)(Ws + j * D + 64 + tx * 4);
            u64t bd[8];
            bd[0] = dup2(bA.x); bd[1] = dup2(bA.y);
            bd[2] = dup2(bA.z); bd[3] = dup2(bA.w);
            bd[4] = dup2(bB.x); bd[5] = dup2(bB.y);
            bd[6] = dup2(bB.z); bd[7] = dup2(bB.w);

#pragma unroll
            for (int p = 0; p < 4; p++)
#pragma unroll
                for (int n = 0; n < 8; n++)
                    acc[p][n] = fma2(a2[p], bd[n], acc[p][n]);
        }
    }

    // Scatter-add into destination accumulator
#pragma unroll
    for (int p = 0; p < 4; p++) {
        int ea = ty * 8 + 2 * p;
        int da = sdst[ea], db = sdst[ea + 1];
        float* pa = g_seg + (size_t)da * D;
        float* pb = g_seg + (size_t)db * D;
#pragma unroll
        for (int n = 0; n < 8; n++) {
            float lo, hi;
            upk2(acc[p][n], lo, hi);
            int o = (n < 4) ? (tx * 4 + n) : (64 + tx * 4 + (n - 4));
            atomicAdd(pa + o, lo);
            atomicAdd(pb + o, hi);
        }
    }
}

// ---------------------------------------------------------------------------
// K3: out = x + gelu(seg/max(cnt,1) + x @ root + bias). 8 nodes per block.
// ---------------------------------------------------------------------------
__global__ __launch_bounds__(128) void out_kernel(
    const float* __restrict__ x,
    const float* __restrict__ root,
    const float* __restrict__ bias,
    float* __restrict__ out)
{
    __shared__ float xsh[8][D];
    const int o  = threadIdx.x;
    const int n0 = blockIdx.x * 8;
    const int nmax = (NNODES - n0 < 8) ? (NNODES - n0) : 8;

    for (int t = threadIdx.x; t < 8 * D; t += 128) {
        int r = t >> 7;
        xsh[r][t & 127] = (r < nmax) ? x[(size_t)(n0 + r) * D + (t & 127)] : 0.0f;
    }
    __syncthreads();

    float acc[8];
#pragma unroll
    for (int r = 0; r < 8; r++) acc[r] = 0.0f;

    for (int i = 0; i < D; i++) {
        float w = root[i * D + o];
#pragma unroll
        for (int r = 0; r < 8; r++) acc[r] += xsh[r][i] * w;
    }

    float bb = bias[o];
    for (int r = 0; r < nmax; r++) {
        int n = n0 + r;
        float cnt  = g_cnt[n];
        float aggr = g_seg[(size_t)n * D + o] / fmaxf(cnt, 1.0f);
        float v = aggr + acc[r] + bb;
        float g = 0.5f * v * (1.0f + erff(v * 0.70710678118654752f));
        out[(size_t)n * D + o] = xsh[r][o] + g;
    }
}

// ---------------------------------------------------------------------------
// Launch
// ---------------------------------------------------------------------------
extern "C" void kernel_launch(void* const* d_in, const int* in_sizes, int n_in,
                              void* d_out, int out_size)
{
    const float* x    = (const float*)d_in[0];
    const int*   ei   = (const int*)d_in[1];     // int32 (jax downcasts int64)
    const float* ea   = (const float*)d_in[2];
    const float* w1   = (const float*)d_in[3];
    const float* b1   = (const float*)d_in[4];
    const float* w2   = (const float*)d_in[5];
    const float* b2   = (const float*)d_in[6];
    const float* root = (const float*)d_in[7];
    const float* bias = (const float*)d_in[8];
    float*       out  = (float*)d_out;

    // Dynamic smem: HsT 129*132 + Ws 129*128 floats + 256 ints
    static const int smem_bytes = (129 * HST + 129 * D) * 4 + 2 * BM * 4;
    cudaFuncSetAttribute(bilinear2_kernel,
                         cudaFuncAttributeMaxDynamicSharedMemorySize, smem_bytes);

    zero_kernel<<<(NNODES * D + 255) / 256, 256>>>();
    count_kernel<<<(E_EDGES + 255) / 256, 256>>>(ei);
    edge_mlp1_kernel<<<E_EDGES / 8, 128>>>(ea, w1, b1);
    bilinear2_kernel<<<E_EDGES / BM, 256, smem_bytes>>>(x, ei, w2, b2);
    out_kernel<<<(NNODES + 7) / 8, 128>>>(x, root, bias, out);
}

// round 10
// speedup vs baseline: 7.1617x; 2.3994x over previous
#include <cuda_runtime.h>
#include <math.h>
#include <stdint.h>

#define E_EDGES 16384
#define NNODES  10000
#define D       128
#define MTILE   64                    // edges per K2 block

// Scratch (device globals: no allocation allowed)
__device__ float g_h[E_EDGES * D];    // relu(edge_attr @ w1 + b1)
__device__ float g_seg[NNODES * D];   // scatter-sum of messages
__device__ float g_cnt[NNODES];       // per-destination edge counts
__device__ uint2 g_w2f[D * 16 * 16 * 32];   // w2 in mma B-fragment layout (tf32)
__device__ uint2 g_b2f[16 * 16 * 32];       // b2 in mma B-fragment layout (tf32)

__device__ __forceinline__ int clamp_node(int v) {
    v = v < 0 ? 0 : v;
    return v >= NNODES ? NNODES - 1 : v;
}

__device__ __forceinline__ uint32_t to_tf32(float f) {
    uint32_t r; asm("cvt.rna.tf32.f32 %0, %1;" : "=r"(r) : "f"(f)); return r;
}

// m16n8k8 tf32 mma: D += A * B  (A row-major frag, B col-major frag)
__device__ __forceinline__ void mma8(float c[4], uint32_t a0, uint32_t a1,
                                     uint32_t a2, uint32_t a3,
                                     uint32_t b0, uint32_t b1) {
    asm("mma.sync.aligned.m16n8k8.row.col.f32.tf32.tf32.f32 "
        "{%0,%1,%2,%3}, {%4,%5,%6,%7}, {%8,%9}, {%0,%1,%2,%3};"
        : "+f"(c[0]), "+f"(c[1]), "+f"(c[2]), "+f"(c[3])
        : "r"(a0), "r"(a1), "r"(a2), "r"(a3), "r"(b0), "r"(b1));
}

// ---------------------------------------------------------------------------
// K0: zero accumulators
// ---------------------------------------------------------------------------
__global__ void zero_kernel() {
    int i = blockIdx.x * blockDim.x + threadIdx.x;
    if (i < NNODES * D) g_seg[i] = 0.0f;
    if (i < NNODES)     g_cnt[i] = 0.0f;
}

// ---------------------------------------------------------------------------
// K0b: per-destination edge counts (edge_index is int32)
// ---------------------------------------------------------------------------
__global__ void count_kernel(const int* __restrict__ ei) {
    int e = blockIdx.x * blockDim.x + threadIdx.x;
    if (e < E_EDGES) {
        int d = clamp_node(ei[E_EDGES + e]);
        atomicAdd(&g_cnt[d], 1.0f);
    }
}

// ---------------------------------------------------------------------------
// K1: h = relu(edge_attr @ w1 + b1). 8 edges per 128-thread block.
// ---------------------------------------------------------------------------
__global__ __launch_bounds__(128) void edge_mlp1_kernel(
    const float* __restrict__ ea,
    const float* __restrict__ w1,
    const float* __restrict__ b1)
{
    __shared__ float sa[8][D];
    const int o  = threadIdx.x;
    const int e0 = blockIdx.x * 8;

    for (int t = threadIdx.x; t < 8 * D; t += 128)
        sa[t >> 7][t & 127] = ea[e0 * D + t];
    __syncthreads();

    float acc[8];
#pragma unroll
    for (int r = 0; r < 8; r++) acc[r] = 0.0f;

    for (int i = 0; i < D; i++) {
        float w = w1[i * D + o];
#pragma unroll
        for (int r = 0; r < 8; r++) acc[r] += sa[r][i] * w;
    }
    float bb = b1[o];
#pragma unroll
    for (int r = 0; r < 8; r++)
        g_h[(size_t)(e0 + r) * D + o] = fmaxf(acc[r] + bb, 0.0f);
}

// ---------------------------------------------------------------------------
// K1b: pack w2 into B-fragment layout (tf32, round-to-nearest).
// Fragment f2 index: ((i*16 + kt)*16 + nt)*32 + lane
//   .x = w2[(kt*8 + lane%4    ) * 16384 + i*128 + nt*8 + lane/4]
//   .y = w2[(kt*8 + lane%4 + 4) * 16384 + i*128 + nt*8 + lane/4]
// ---------------------------------------------------------------------------
__global__ __launch_bounds__(256) void pack_w2_kernel(const float* __restrict__ w2)
{
    int f = blockIdx.x * 256 + threadIdx.x;          // 0 .. 2^20-1
    int lane = f & 31, nt = (f >> 5) & 15, kt = (f >> 9) & 15, i = f >> 13;
    int k = kt * 8 + (lane & 3);
    int n = nt * 8 + (lane >> 2);
    uint2 v;
    v.x = to_tf32(w2[(size_t)k * (D * D) + i * D + n]);
    v.y = to_tf32(w2[(size_t)(k + 4) * (D * D) + i * D + n]);
    g_w2f[f] = v;
}

__global__ __launch_bounds__(256) void pack_b2_kernel(const float* __restrict__ b2)
{
    int f = blockIdx.x * 256 + threadIdx.x;          // 0 .. 8191
    int lane = f & 31, nt = (f >> 5) & 15, kt = f >> 9;
    int k = kt * 8 + (lane & 3);
    int n = nt * 8 + (lane >> 2);
    uint2 v;
    v.x = to_tf32(b2[k * D + n]);
    v.y = to_tf32(b2[(k + 4) * D + n]);
    g_b2f[f] = v;
}

// ---------------------------------------------------------------------------
// K2: HMMA tf32 chained bilinear.
//   msg[e,o] = sum_i x[src[e],i] * ( sum_k h[e,k]*w2[k][i*128+o] + b2[i*128+o] )
// Block = 64 edges, 8 warps = 4 M-groups x 2 N-groups(64 outs).
// H lives in A-fragments (registers); per i A-frag scaled by x[:,i];
// B-fragments streamed by LDG.64 from pre-packed g_w2f (L1-resident).
// b2 handled as extra iteration with A = gathered x rows.
// ---------------------------------------------------------------------------
__global__ __launch_bounds__(256, 1) void bilinear_hmma_kernel(
    const float* __restrict__ x, const int* __restrict__ ei)
{
    const int lane = threadIdx.x & 31, wid = threadIdx.x >> 5;
    const int mg = wid >> 1, ng = wid & 1;
    const int e0 = blockIdx.x * MTILE + mg * 16;
    const int g  = lane >> 2, c = lane & 3;

    const int srcA = clamp_node(ei[e0 + g]);
    const int srcB = clamp_node(ei[e0 + g + 8]);

    // H fragments (row-major A): a0=(g,c) a1=(g+8,c) a2=(g,c+4) a3=(g+8,c+4)
    float hA[16][4];
    {
        const float* hrA = g_h + (size_t)(e0 + g) * D;
        const float* hrB = g_h + (size_t)(e0 + g + 8) * D;
#pragma unroll
        for (int kt = 0; kt < 16; kt++) {
            hA[kt][0] = hrA[kt * 8 + c];
            hA[kt][1] = hrB[kt * 8 + c];
            hA[kt][2] = hrA[kt * 8 + c + 4];
            hA[kt][3] = hrB[kt * 8 + c + 4];
        }
    }

    float acc[8][4];
#pragma unroll
    for (int nt = 0; nt < 8; nt++)
#pragma unroll
        for (int j = 0; j < 4; j++) acc[nt][j] = 0.0f;

    const float* xrA = x + (size_t)srcA * D;
    const float* xrB = x + (size_t)srcB * D;

    for (int i = 0; i < D; i++) {
        const float xg = __ldg(xrA + i);
        const float xh = __ldg(xrB + i);
        const uint2* wf = g_w2f + ((size_t)i * 16 * 16 + ng * 8) * 32 + lane;
#pragma unroll 4
        for (int kt = 0; kt < 16; kt++) {
            uint32_t a0 = __float_as_uint(hA[kt][0] * xg);
            uint32_t a1 = __float_as_uint(hA[kt][1] * xh);
            uint32_t a2 = __float_as_uint(hA[kt][2] * xg);
            uint32_t a3 = __float_as_uint(hA[kt][3] * xh);
            const uint2* wk = wf + (size_t)kt * 16 * 32;
#pragma unroll
            for (int nt = 0; nt < 8; nt++) {
                uint2 b = __ldg(wk + nt * 32);
                mma8(acc[nt], a0, a1, a2, a3, b.x, b.y);
            }
        }
    }

    // b2 term: A = gathered x rows (truncated to tf32 by HW)
    {
        const uint2* bf = g_b2f + (size_t)(ng * 8) * 32 + lane;
#pragma unroll 4
        for (int kt = 0; kt < 16; kt++) {
            uint32_t a0 = __float_as_uint(xrA[kt * 8 + c]);
            uint32_t a1 = __float_as_uint(xrB[kt * 8 + c]);
            uint32_t a2 = __float_as_uint(xrA[kt * 8 + c + 4]);
            uint32_t a3 = __float_as_uint(xrB[kt * 8 + c + 4]);
            const uint2* bk = bf + (size_t)kt * 16 * 32;
#pragma unroll
            for (int nt = 0; nt < 8; nt++) {
                uint2 b = __ldg(bk + nt * 32);
                mma8(acc[nt], a0, a1, a2, a3, b.x, b.y);
            }
        }
    }

    // Epilogue: D frag c0=(g, 2c) c1=(g, 2c+1) c2=(g+8, 2c) c3=(g+8, 2c+1)
    const int dA = clamp_node(ei[E_EDGES + e0 + g]);
    const int dB = clamp_node(ei[E_EDGES + e0 + g + 8]);
    float* pA = g_seg + (size_t)dA * D + ng * 64 + 2 * c;
    float* pB = g_seg + (size_t)dB * D + ng * 64 + 2 * c;
#pragma unroll
    for (int nt = 0; nt < 8; nt++) {
        atomicAdd(pA + nt * 8,     acc[nt][0]);
        atomicAdd(pA + nt * 8 + 1, acc[nt][1]);
        atomicAdd(pB + nt * 8,     acc[nt][2]);
        atomicAdd(pB + nt * 8 + 1, acc[nt][3]);
    }
}

// ---------------------------------------------------------------------------
// K3: out = x + gelu(seg/max(cnt,1) + x @ root + bias). 8 nodes per block.
// ---------------------------------------------------------------------------
__global__ __launch_bounds__(128) void out_kernel(
    const float* __restrict__ x,
    const float* __restrict__ root,
    const float* __restrict__ bias,
    float* __restrict__ out)
{
    __shared__ float xsh[8][D];
    const int o  = threadIdx.x;
    const int n0 = blockIdx.x * 8;
    const int nmax = (NNODES - n0 < 8) ? (NNODES - n0) : 8;

    for (int t = threadIdx.x; t < 8 * D; t += 128) {
        int r = t >> 7;
        xsh[r][t & 127] = (r < nmax) ? x[(size_t)(n0 + r) * D + (t & 127)] : 0.0f;
    }
    __syncthreads();

    float acc[8];
#pragma unroll
    for (int r = 0; r < 8; r++) acc[r] = 0.0f;

    for (int i = 0; i < D; i++) {
        float w = root[i * D + o];
#pragma unroll
        for (int r = 0; r < 8; r++) acc[r] += xsh[r][i] * w;
    }

    float bb = bias[o];
    for (int r = 0; r < nmax; r++) {
        int n = n0 + r;
        float cnt  = g_cnt[n];
        float aggr = g_seg[(size_t)n * D + o] / fmaxf(cnt, 1.0f);
        float v = aggr + acc[r] + bb;
        float g = 0.5f * v * (1.0f + erff(v * 0.70710678118654752f));
        out[(size_t)n * D + o] = xsh[r][o] + g;
    }
}

// ---------------------------------------------------------------------------
// Launch
// ---------------------------------------------------------------------------
extern "C" void kernel_launch(void* const* d_in, const int* in_sizes, int n_in,
                              void* d_out, int out_size)
{
    const float* x    = (const float*)d_in[0];
    const int*   ei   = (const int*)d_in[1];     // int32 (jax downcasts int64)
    const float* ea   = (const float*)d_in[2];
    const float* w1   = (const float*)d_in[3];
    const float* b1   = (const float*)d_in[4];
    const float* w2   = (const float*)d_in[5];
    const float* b2   = (const float*)d_in[6];
    const float* root = (const float*)d_in[7];
    const float* bias = (const float*)d_in[8];
    float*       out  = (float*)d_out;

    zero_kernel<<<(NNODES * D + 255) / 256, 256>>>();
    count_kernel<<<(E_EDGES + 255) / 256, 256>>>(ei);
    pack_w2_kernel<<<(D * 16 * 16 * 32) / 256, 256>>>(w2);
    pack_b2_kernel<<<(16 * 16 * 32) / 256, 256>>>(b2);
    edge_mlp1_kernel<<<E_EDGES / 8, 128>>>(ea, w1, b1);
    bilinear_hmma_kernel<<<E_EDGES / MTILE, 256>>>(x, ei);
    out_kernel<<<(NNODES + 7) / 8, 128>>>(x, root, bias, out);
}

// round 11
// speedup vs baseline: 9.2040x; 1.2852x over previous
#include <cuda_runtime.h>
#include <math.h>
#include <stdint.h>

#define E_EDGES 16384
#define NNODES  10000
#define D       128

// Scratch (device globals: no allocation allowed)
__device__ float g_h[E_EDGES * D];    // relu(edge_attr @ w1 + b1)
__device__ float g_seg[NNODES * D];   // scatter-sum of messages
__device__ float g_cnt[NNODES];       // per-destination edge counts
__device__ uint4 g_w2f4[D * 16 * 8 * 32];   // w2, paired B-fragments (tf32)
__device__ uint4 g_b2f4[16 * 8 * 32];       // b2, paired B-fragments (tf32)

__device__ __forceinline__ int clamp_node(int v) {
    v = v < 0 ? 0 : v;
    return v >= NNODES ? NNODES - 1 : v;
}

__device__ __forceinline__ uint32_t to_tf32(float f) {
    uint32_t r; asm("cvt.rna.tf32.f32 %0, %1;" : "=r"(r) : "f"(f)); return r;
}
__device__ __forceinline__ uint32_t fu(float f) { return __float_as_uint(f); }

// m16n8k8 tf32 mma: D += A * B  (A row-major frag, B col-major frag)
__device__ __forceinline__ void mma8(float c[4], uint32_t a0, uint32_t a1,
                                     uint32_t a2, uint32_t a3,
                                     uint32_t b0, uint32_t b1) {
    asm("mma.sync.aligned.m16n8k8.row.col.f32.tf32.tf32.f32 "
        "{%0,%1,%2,%3}, {%4,%5,%6,%7}, {%8,%9}, {%0,%1,%2,%3};"
        : "+f"(c[0]), "+f"(c[1]), "+f"(c[2]), "+f"(c[3])
        : "r"(a0), "r"(a1), "r"(a2), "r"(a3), "r"(b0), "r"(b1));
}

// ---------------------------------------------------------------------------
// K0: zero accumulators
// ---------------------------------------------------------------------------
__global__ void zero_kernel() {
    int i = blockIdx.x * blockDim.x + threadIdx.x;
    if (i < NNODES * D) g_seg[i] = 0.0f;
    if (i < NNODES)     g_cnt[i] = 0.0f;
}

// ---------------------------------------------------------------------------
// K0b: per-destination edge counts (edge_index is int32)
// ---------------------------------------------------------------------------
__global__ void count_kernel(const int* __restrict__ ei) {
    int e = blockIdx.x * blockDim.x + threadIdx.x;
    if (e < E_EDGES) {
        int d = clamp_node(ei[E_EDGES + e]);
        atomicAdd(&g_cnt[d], 1.0f);
    }
}

// ---------------------------------------------------------------------------
// K1: h = relu(edge_attr @ w1 + b1). 8 edges per 128-thread block.
// ---------------------------------------------------------------------------
__global__ __launch_bounds__(128) void edge_mlp1_kernel(
    const float* __restrict__ ea,
    const float* __restrict__ w1,
    const float* __restrict__ b1)
{
    __shared__ float sa[8][D];
    const int o  = threadIdx.x;
    const int e0 = blockIdx.x * 8;

    for (int t = threadIdx.x; t < 8 * D; t += 128)
        sa[t >> 7][t & 127] = ea[e0 * D + t];
    __syncthreads();

    float acc[8];
#pragma unroll
    for (int r = 0; r < 8; r++) acc[r] = 0.0f;

    for (int i = 0; i < D; i++) {
        float w = w1[i * D + o];
#pragma unroll
        for (int r = 0; r < 8; r++) acc[r] += sa[r][i] * w;
    }
    float bb = b1[o];
#pragma unroll
    for (int r = 0; r < 8; r++)
        g_h[(size_t)(e0 + r) * D + o] = fmaxf(acc[r] + bb, 0.0f);
}

// ---------------------------------------------------------------------------
// K1b: pack w2/b2 into PAIRED B-fragment layout (uint4 = two n-tiles).
// Index: ((i*16 + kt)*8 + ntp)*32 + lane
//   .x/.y = B frag (k=kt*8+lane%4 / +4) for n = ntp*16 + lane/4
//   .z/.w = same for n + 8
// ---------------------------------------------------------------------------
__global__ __launch_bounds__(256) void pack_w2_kernel(const float* __restrict__ w2)
{
    int f = blockIdx.x * 256 + threadIdx.x;          // 0 .. 524287
    int lane = f & 31, ntp = (f >> 5) & 7, kt = (f >> 8) & 15, i = f >> 12;
    int k  = kt * 8 + (lane & 3);
    int n0 = ntp * 16 + (lane >> 2);
    uint4 v;
    v.x = to_tf32(w2[(size_t)k * (D * D) + i * D + n0]);
    v.y = to_tf32(w2[(size_t)(k + 4) * (D * D) + i * D + n0]);
    v.z = to_tf32(w2[(size_t)k * (D * D) + i * D + n0 + 8]);
    v.w = to_tf32(w2[(size_t)(k + 4) * (D * D) + i * D + n0 + 8]);
    g_w2f4[f] = v;
}

__global__ __launch_bounds__(256) void pack_b2_kernel(const float* __restrict__ b2)
{
    int f = blockIdx.x * 256 + threadIdx.x;          // 0 .. 4095
    int lane = f & 31, ntp = (f >> 5) & 7, kt = f >> 8;
    int k  = kt * 8 + (lane & 3);
    int n0 = ntp * 16 + (lane >> 2);
    uint4 v;
    v.x = to_tf32(b2[k * D + n0]);
    v.y = to_tf32(b2[(k + 4) * D + n0]);
    v.z = to_tf32(b2[k * D + n0 + 8]);
    v.w = to_tf32(b2[(k + 4) * D + n0 + 8]);
    g_b2f4[f] = v;
}

// ---------------------------------------------------------------------------
// K2: HMMA tf32 chained bilinear, v2.
// Block = 128 edges (single wave: 128 blocks). 8 warps = 4 mg x 2 ng.
// Warp: 32 edges (2 m-frags) x 64 outs. Each uint4 B load feeds 4 MMAs.
// ---------------------------------------------------------------------------
__global__ __launch_bounds__(256, 1) void bilinear_hmma_kernel(
    const float* __restrict__ x, const int* __restrict__ ei)
{
    const int lane = threadIdx.x & 31, wid = threadIdx.x >> 5;
    const int mg = wid >> 1, ng = wid & 1;
    const int e0 = blockIdx.x * 128 + mg * 32;
    const int g  = lane >> 2, c = lane & 3;

    const int sA0 = clamp_node(ei[e0 + g]);
    const int sB0 = clamp_node(ei[e0 + g + 8]);
    const int sA1 = clamp_node(ei[e0 + 16 + g]);
    const int sB1 = clamp_node(ei[e0 + 16 + g + 8]);

    // H fragments for both m-frags (row-major A layout)
    float h0[16][4], h1[16][4];
    {
        const float* rA0 = g_h + (size_t)(e0 + g) * D;
        const float* rB0 = g_h + (size_t)(e0 + g + 8) * D;
        const float* rA1 = g_h + (size_t)(e0 + 16 + g) * D;
        const float* rB1 = g_h + (size_t)(e0 + 16 + g + 8) * D;
#pragma unroll
        for (int kt = 0; kt < 16; kt++) {
            h0[kt][0] = rA0[kt * 8 + c];     h0[kt][1] = rB0[kt * 8 + c];
            h0[kt][2] = rA0[kt * 8 + c + 4]; h0[kt][3] = rB0[kt * 8 + c + 4];
            h1[kt][0] = rA1[kt * 8 + c];     h1[kt][1] = rB1[kt * 8 + c];
            h1[kt][2] = rA1[kt * 8 + c + 4]; h1[kt][3] = rB1[kt * 8 + c + 4];
        }
    }

    float acc0[8][4], acc1[8][4];
#pragma unroll
    for (int nt = 0; nt < 8; nt++)
#pragma unroll
        for (int j = 0; j < 4; j++) { acc0[nt][j] = 0.0f; acc1[nt][j] = 0.0f; }

    const float* xA0 = x + (size_t)sA0 * D;
    const float* xB0 = x + (size_t)sB0 * D;
    const float* xA1 = x + (size_t)sA1 * D;
    const float* xB1 = x + (size_t)sB1 * D;

    for (int i = 0; i < D; i++) {
        const float x0g = __ldg(xA0 + i), x0h = __ldg(xB0 + i);
        const float x1g = __ldg(xA1 + i), x1h = __ldg(xB1 + i);
        const uint4* wf = g_w2f4 + ((size_t)i * 16 * 8 + ng * 4) * 32 + lane;
#pragma unroll 2
        for (int kt = 0; kt < 16; kt++) {
            const uint32_t a00 = fu(h0[kt][0] * x0g), a01 = fu(h0[kt][1] * x0h);
            const uint32_t a02 = fu(h0[kt][2] * x0g), a03 = fu(h0[kt][3] * x0h);
            const uint32_t a10 = fu(h1[kt][0] * x1g), a11 = fu(h1[kt][1] * x1h);
            const uint32_t a12 = fu(h1[kt][2] * x1g), a13 = fu(h1[kt][3] * x1h);
            const uint4* wk = wf + (size_t)kt * 8 * 32;
#pragma unroll
            for (int ntp = 0; ntp < 4; ntp++) {
                uint4 b = __ldg(wk + ntp * 32);
                mma8(acc0[2 * ntp],     a00, a01, a02, a03, b.x, b.y);
                mma8(acc0[2 * ntp + 1], a00, a01, a02, a03, b.z, b.w);
                mma8(acc1[2 * ntp],     a10, a11, a12, a13, b.x, b.y);
                mma8(acc1[2 * ntp + 1], a10, a11, a12, a13, b.z, b.w);
            }
        }
    }

    // b2 term: A = gathered x rows (HW-truncated to tf32)
    {
        const uint4* bf = g_b2f4 + (size_t)(ng * 4) * 32 + lane;
#pragma unroll 2
        for (int kt = 0; kt < 16; kt++) {
            const uint32_t a00 = fu(xA0[kt * 8 + c]),     a01 = fu(xB0[kt * 8 + c]);
            const uint32_t a02 = fu(xA0[kt * 8 + c + 4]), a03 = fu(xB0[kt * 8 + c + 4]);
            const uint32_t a10 = fu(xA1[kt * 8 + c]),     a11 = fu(xB1[kt * 8 + c]);
            const uint32_t a12 = fu(xA1[kt * 8 + c + 4]), a13 = fu(xB1[kt * 8 + c + 4]);
            const uint4* bk = bf + (size_t)kt * 8 * 32;
#pragma unroll
            for (int ntp = 0; ntp < 4; ntp++) {
                uint4 b = __ldg(bk + ntp * 32);
                mma8(acc0[2 * ntp],     a00, a01, a02, a03, b.x, b.y);
                mma8(acc0[2 * ntp + 1], a00, a01, a02, a03, b.z, b.w);
                mma8(acc1[2 * ntp],     a10, a11, a12, a13, b.x, b.y);
                mma8(acc1[2 * ntp + 1], a10, a11, a12, a13, b.z, b.w);
            }
        }
    }

    // Epilogue: D frag (row g / g+8, col 2c / 2c+1) for both m-frags
    const int dA0 = clamp_node(ei[E_EDGES + e0 + g]);
    const int dB0 = clamp_node(ei[E_EDGES + e0 + g + 8]);
    const int dA1 = clamp_node(ei[E_EDGES + e0 + 16 + g]);
    const int dB1 = clamp_node(ei[E_EDGES + e0 + 16 + g + 8]);
    float* pA0 = g_seg + (size_t)dA0 * D + ng * 64 + 2 * c;
    float* pB0 = g_seg + (size_t)dB0 * D + ng * 64 + 2 * c;
    float* pA1 = g_seg + (size_t)dA1 * D + ng * 64 + 2 * c;
    float* pB1 = g_seg + (size_t)dB1 * D + ng * 64 + 2 * c;
#pragma unroll
    for (int nt = 0; nt < 8; nt++) {
        atomicAdd(pA0 + nt * 8,     acc0[nt][0]);
        atomicAdd(pA0 + nt * 8 + 1, acc0[nt][1]);
        atomicAdd(pB0 + nt * 8,     acc0[nt][2]);
        atomicAdd(pB0 + nt * 8 + 1, acc0[nt][3]);
        atomicAdd(pA1 + nt * 8,     acc1[nt][0]);
        atomicAdd(pA1 + nt * 8 + 1, acc1[nt][1]);
        atomicAdd(pB1 + nt * 8,     acc1[nt][2]);
        atomicAdd(pB1 + nt * 8 + 1, acc1[nt][3]);
    }
}

// ---------------------------------------------------------------------------
// K3: out = x + gelu(seg/max(cnt,1) + x @ root + bias). 8 nodes per block.
// ---------------------------------------------------------------------------
__global__ __launch_bounds__(128) void out_kernel(
    const float* __restrict__ x,
    const float* __restrict__ root,
    const float* __restrict__ bias,
    float* __restrict__ out)
{
    __shared__ float xsh[8][D];
    const int o  = threadIdx.x;
    const int n0 = blockIdx.x * 8;
    const int nmax = (NNODES - n0 < 8) ? (NNODES - n0) : 8;

    for (int t = threadIdx.x; t < 8 * D; t += 128) {
        int r = t >> 7;
        xsh[r][t & 127] = (r < nmax) ? x[(size_t)(n0 + r) * D + (t & 127)] : 0.0f;
    }
    __syncthreads();

    float acc[8];
#pragma unroll
    for (int r = 0; r < 8; r++) acc[r] = 0.0f;

    for (int i = 0; i < D; i++) {
        float w = root[i * D + o];
#pragma unroll
        for (int r = 0; r < 8; r++) acc[r] += xsh[r][i] * w;
    }

    float bb = bias[o];
    for (int r = 0; r < nmax; r++) {
        int n = n0 + r;
        float cnt  = g_cnt[n];
        float aggr = g_seg[(size_t)n * D + o] / fmaxf(cnt, 1.0f);
        float v = aggr + acc[r] + bb;
        float g = 0.5f * v * (1.0f + erff(v * 0.70710678118654752f));
        out[(size_t)n * D + o] = xsh[r][o] + g;
    }
}

// ---------------------------------------------------------------------------
// Launch
// ---------------------------------------------------------------------------
extern "C" void kernel_launch(void* const* d_in, const int* in_sizes, int n_in,
                              void* d_out, int out_size)
{
    const float* x    = (const float*)d_in[0];
    const int*   ei   = (const int*)d_in[1];     // int32 (jax downcasts int64)
    const float* ea   = (const float*)d_in[2];
    const float* w1   = (const float*)d_in[3];
    const float* b1   = (const float*)d_in[4];
    const float* w2   = (const float*)d_in[5];
    const float* b2   = (const float*)d_in[6];
    const float* root = (const float*)d_in[7];
    const float* bias = (const float*)d_in[8];
    float*       out  = (float*)d_out;

    zero_kernel<<<(NNODES * D + 255) / 256, 256>>>();
    count_kernel<<<(E_EDGES + 255) / 256, 256>>>(ei);
    pack_w2_kernel<<<(D * 16 * 8 * 32) / 256, 256>>>(w2);
    pack_b2_kernel<<<(16 * 8 * 32) / 256, 256>>>(b2);
    edge_mlp1_kernel<<<E_EDGES / 8, 128>>>(ea, w1, b1);
    bilinear_hmma_kernel<<<E_EDGES / 128, 256>>>(x, ei);
    out_kernel<<<(NNODES + 7) / 8, 128>>>(x, root, bias, out);
}

// round 13
// speedup vs baseline: 13.5791x; 1.4754x over previous
#include <cuda_runtime.h>
#include <math.h>
#include <stdint.h>

#define E_EDGES 16384
#define NNODES  10000
#define D       128

// Scratch (device globals: no allocation allowed)
__device__ float g_h[E_EDGES * D];    // relu(edge_attr @ w1 + b1)
__device__ float g_seg[NNODES * D];   // scatter-sum of messages
__device__ float g_cnt[NNODES];       // per-destination edge counts
__device__ uint4 g_w2f4[D * 8 * 8 * 32];   // w2, fp16 paired B-fragments (4 MB)
__device__ uint4 g_b2f4[8 * 8 * 32];       // b2, fp16 paired B-fragments

__device__ __forceinline__ int clamp_node(int v) {
    v = v < 0 ? 0 : v;
    return v >= NNODES ? NNODES - 1 : v;
}

// pack two f32 -> half2 register (lo in low half), single rounding each
__device__ __forceinline__ uint32_t h2f(float lo, float hi) {
    uint32_t r;
    asm("cvt.rn.f16x2.f32 %0, %1, %2;" : "=r"(r) : "f"(hi), "f"(lo));
    return r;
}

// m16n8k16 fp16 mma, fp32 accumulate: D += A * B
__device__ __forceinline__ void mma16(float c[4], uint32_t a0, uint32_t a1,
                                      uint32_t a2, uint32_t a3,
                                      uint32_t b0, uint32_t b1) {
    asm("mma.sync.aligned.m16n8k16.row.col.f32.f16.f16.f32 "
        "{%0,%1,%2,%3}, {%4,%5,%6,%7}, {%8,%9}, {%0,%1,%2,%3};"
        : "+f"(c[0]), "+f"(c[1]), "+f"(c[2]), "+f"(c[3])
        : "r"(a0), "r"(a1), "r"(a2), "r"(a3), "r"(b0), "r"(b1));
}

// ---------------------------------------------------------------------------
// K0: zero accumulators
// ---------------------------------------------------------------------------
__global__ void zero_kernel() {
    int i = blockIdx.x * blockDim.x + threadIdx.x;
    if (i < NNODES * D) g_seg[i] = 0.0f;
    if (i < NNODES)     g_cnt[i] = 0.0f;
}

// ---------------------------------------------------------------------------
// K0b: per-destination edge counts (edge_index is int32)
// ---------------------------------------------------------------------------
__global__ void count_kernel(const int* __restrict__ ei) {
    int e = blockIdx.x * blockDim.x + threadIdx.x;
    if (e < E_EDGES) {
        int d = clamp_node(ei[E_EDGES + e]);
        atomicAdd(&g_cnt[d], 1.0f);
    }
}

// ---------------------------------------------------------------------------
// K1: h = relu(edge_attr @ w1 + b1). 8 edges per 128-thread block.
// ---------------------------------------------------------------------------
__global__ __launch_bounds__(128) void edge_mlp1_kernel(
    const float* __restrict__ ea,
    const float* __restrict__ w1,
    const float* __restrict__ b1)
{
    __shared__ float sa[8][D];
    const int o  = threadIdx.x;
    const int e0 = blockIdx.x * 8;

    for (int t = threadIdx.x; t < 8 * D; t += 128)
        sa[t >> 7][t & 127] = ea[e0 * D + t];
    __syncthreads();

    float acc[8];
#pragma unroll
    for (int r = 0; r < 8; r++) acc[r] = 0.0f;

    for (int i = 0; i < D; i++) {
        float w = w1[i * D + o];
#pragma unroll
        for (int r = 0; r < 8; r++) acc[r] += sa[r][i] * w;
    }
    float bb = b1[o];
#pragma unroll
    for (int r = 0; r < 8; r++)
        g_h[(size_t)(e0 + r) * D + o] = fmaxf(acc[r] + bb, 0.0f);
}

// ---------------------------------------------------------------------------
// K1b: pack w2 AND b2 into fp16 paired B-fragment layout (fused kernel).
// Fragment index: ((i*8 + kt)*8 + slot)*32 + lane  (slot = global n-tile pair)
//   .x = half2(w2[k0  ][na], w2[k0+1][na])   k0 = kt*16 + 2*(lane%4)
//   .y = half2(w2[k0+8][na], w2[k0+9][na])   na = (2*slot)*8 + lane/4
//   .z/.w = same at nb = na + 8
// ---------------------------------------------------------------------------
#define W2_PACK_BLOCKS (D * 8 * 8 * 32 / 256)   // 1024

__global__ __launch_bounds__(256) void pack_kernel(
    const float* __restrict__ w2, const float* __restrict__ b2)
{
    if (blockIdx.x < W2_PACK_BLOCKS) {
        int f = blockIdx.x * 256 + threadIdx.x;       // 0 .. 262143
        int lane = f & 31, slot = (f >> 5) & 7, kt = (f >> 8) & 7, i = f >> 11;
        int c = lane & 3, g = lane >> 2;
        int k0 = kt * 16 + 2 * c;
        int na = (2 * slot) * 8 + g, nb = na + 8;
        const size_t rs = (size_t)D * D;
        const float* p = w2 + (size_t)k0 * rs + (size_t)i * D;
        uint4 v;
        v.x = h2f(p[na],          p[rs + na]);
        v.y = h2f(p[8 * rs + na], p[9 * rs + na]);
        v.z = h2f(p[nb],          p[rs + nb]);
        v.w = h2f(p[8 * rs + nb], p[9 * rs + nb]);
        g_w2f4[f] = v;
    } else {
        int f = (blockIdx.x - W2_PACK_BLOCKS) * 256 + threadIdx.x;  // 0..2047
        int lane = f & 31, slot = (f >> 5) & 7, kt = f >> 8;
        int c = lane & 3, g = lane >> 2;
        int k0 = kt * 16 + 2 * c;
        int na = (2 * slot) * 8 + g, nb = na + 8;
        const float* p = b2 + (size_t)k0 * D;
        uint4 v;
        v.x = h2f(p[na],         p[D + na]);
        v.y = h2f(p[8 * D + na], p[9 * D + na]);
        v.z = h2f(p[nb],         p[D + nb]);
        v.w = h2f(p[8 * D + nb], p[9 * D + nb]);
        g_b2f4[f] = v;
    }
}

// ---------------------------------------------------------------------------
// K2: fp16 m16n8k16 HMMA chained bilinear.
//   msg[e,o] = sum_i x[src[e],i] * ( sum_k h[e,k]*w2[k][i*128+o] + b2[i*128+o] )
// Block = 128 edges, single wave (128 blocks). 8 warps = 4 mg x 2 ng.
// Warp: 32 edges (2 m-frags) x 64 outs. A = h*x computed in fp32, rounded
// once to half2. Each uint4 B load feeds 4 MMAs. fp32 accumulate.
// ---------------------------------------------------------------------------
__global__ __launch_bounds__(256, 1) void bilinear_hmma16_kernel(
    const float* __restrict__ x, const int* __restrict__ ei)
{
    const int lane = threadIdx.x & 31, wid = threadIdx.x >> 5;
    const int mg = wid >> 1, ng = wid & 1;
    const int e0 = blockIdx.x * 128 + mg * 32;
    const int g  = lane >> 2, c = lane & 3;

    const int sA0 = clamp_node(ei[e0 + g]);
    const int sB0 = clamp_node(ei[e0 + g + 8]);
    const int sA1 = clamp_node(ei[e0 + 16 + g]);
    const int sB1 = clamp_node(ei[e0 + 16 + g + 8]);

    // H elements needed for m16n8k16 A-frags: k = kt*16 + {2c,2c+1,2c+8,2c+9}
    // h[kt][0..7] = {A:2c, A:2c+1, B:2c, B:2c+1, A:2c+8, A:2c+9, B:2c+8, B:2c+9}
    float h0[8][8], h1[8][8];
    {
        const float* rA0 = g_h + (size_t)(e0 + g) * D;
        const float* rB0 = g_h + (size_t)(e0 + g + 8) * D;
        const float* rA1 = g_h + (size_t)(e0 + 16 + g) * D;
        const float* rB1 = g_h + (size_t)(e0 + 16 + g + 8) * D;
#pragma unroll
        for (int kt = 0; kt < 8; kt++) {
            int b = kt * 16 + 2 * c;
            float2 pA = *(const float2*)(rA0 + b);
            float2 pB = *(const float2*)(rB0 + b);
            float2 qA = *(const float2*)(rA0 + b + 8);
            float2 qB = *(const float2*)(rB0 + b + 8);
            h0[kt][0] = pA.x; h0[kt][1] = pA.y; h0[kt][2] = pB.x; h0[kt][3] = pB.y;
            h0[kt][4] = qA.x; h0[kt][5] = qA.y; h0[kt][6] = qB.x; h0[kt][7] = qB.y;
            float2 uA = *(const float2*)(rA1 + b);
            float2 uB = *(const float2*)(rB1 + b);
            float2 vA = *(const float2*)(rA1 + b + 8);
            float2 vB = *(const float2*)(rB1 + b + 8);
            h1[kt][0] = uA.x; h1[kt][1] = uA.y; h1[kt][2] = uB.x; h1[kt][3] = uB.y;
            h1[kt][4] = vA.x; h1[kt][5] = vA.y; h1[kt][6] = vB.x; h1[kt][7] = vB.y;
        }
    }

    float acc0[8][4], acc1[8][4];
#pragma unroll
    for (int nt = 0; nt < 8; nt++)
#pragma unroll
        for (int j = 0; j < 4; j++) { acc0[nt][j] = 0.0f; acc1[nt][j] = 0.0f; }

    const float* xA0 = x + (size_t)sA0 * D;
    const float* xB0 = x + (size_t)sB0 * D;
    const float* xA1 = x + (size_t)sA1 * D;
    const float* xB1 = x + (size_t)sB1 * D;

    for (int i = 0; i < D; i++) {
        const float x0g = __ldg(xA0 + i), x0h = __ldg(xB0 + i);
        const float x1g = __ldg(xA1 + i), x1h = __ldg(xB1 + i);
        const uint4* wf = g_w2f4 + ((size_t)(i * 8) * 8 + ng * 4) * 32 + lane;
#pragma unroll
        for (int kt = 0; kt < 8; kt++) {
            const uint32_t a00 = h2f(h0[kt][0] * x0g, h0[kt][1] * x0g);
            const uint32_t a01 = h2f(h0[kt][2] * x0h, h0[kt][3] * x0h);
            const uint32_t a02 = h2f(h0[kt][4] * x0g, h0[kt][5] * x0g);
            const uint32_t a03 = h2f(h0[kt][6] * x0h, h0[kt][7] * x0h);
            const uint32_t a10 = h2f(h1[kt][0] * x1g, h1[kt][1] * x1g);
            const uint32_t a11 = h2f(h1[kt][2] * x1h, h1[kt][3] * x1h);
            const uint32_t a12 = h2f(h1[kt][4] * x1g, h1[kt][5] * x1g);
            const uint32_t a13 = h2f(h1[kt][6] * x1h, h1[kt][7] * x1h);
            const uint4* wk = wf + (size_t)kt * 8 * 32;
#pragma unroll
            for (int ntp = 0; ntp < 4; ntp++) {
                uint4 b = __ldg(wk + ntp * 32);
                mma16(acc0[2 * ntp],     a00, a01, a02, a03, b.x, b.y);
                mma16(acc0[2 * ntp + 1], a00, a01, a02, a03, b.z, b.w);
                mma16(acc1[2 * ntp],     a10, a11, a12, a13, b.x, b.y);
                mma16(acc1[2 * ntp + 1], a10, a11, a12, a13, b.z, b.w);
            }
        }
    }

    // b2 term: A = gathered x rows (fp32 -> single rounding to fp16)
    {
        const uint4* bf = g_b2f4 + (size_t)(ng * 4) * 32 + lane;
#pragma unroll
        for (int kt = 0; kt < 8; kt++) {
            int b = kt * 16 + 2 * c;
            const uint32_t a00 = h2f(xA0[b],     xA0[b + 1]);
            const uint32_t a01 = h2f(xB0[b],     xB0[b + 1]);
            const uint32_t a02 = h2f(xA0[b + 8], xA0[b + 9]);
            const uint32_t a03 = h2f(xB0[b + 8], xB0[b + 9]);
            const uint32_t a10 = h2f(xA1[b],     xA1[b + 1]);
            const uint32_t a11 = h2f(xB1[b],     xB1[b + 1]);
            const uint32_t a12 = h2f(xA1[b + 8], xA1[b + 9]);
            const uint32_t a13 = h2f(xB1[b + 8], xB1[b + 9]);
            const uint4* bk = bf + (size_t)kt * 8 * 32;
#pragma unroll
            for (int ntp = 0; ntp < 4; ntp++) {
                uint4 b2v = __ldg(bk + ntp * 32);
                mma16(acc0[2 * ntp],     a00, a01, a02, a03, b2v.x, b2v.y);
                mma16(acc0[2 * ntp + 1], a00, a01, a02, a03, b2v.z, b2v.w);
                mma16(acc1[2 * ntp],     a10, a11, a12, a13, b2v.x, b2v.y);
                mma16(acc1[2 * ntp + 1], a10, a11, a12, a13, b2v.z, b2v.w);
            }
        }
    }

    // Epilogue: D frag rows g/g+8, cols 2c/2c+1 (same layout as m16n8k8)
    const int dA0 = clamp_node(ei[E_EDGES + e0 + g]);
    const int dB0 = clamp_node(ei[E_EDGES + e0 + g + 8]);
    const int dA1 = clamp_node(ei[E_EDGES + e0 + 16 + g]);
    const int dB1 = clamp_node(ei[E_EDGES + e0 + 16 + g + 8]);
    float* pA0 = g_seg + (size_t)dA0 * D + ng * 64 + 2 * c;
    float* pB0 = g_seg + (size_t)dB0 * D + ng * 64 + 2 * c;
    float* pA1 = g_seg + (size_t)dA1 * D + ng * 64 + 2 * c;
    float* pB1 = g_seg + (size_t)dB1 * D + ng * 64 + 2 * c;
#pragma unroll
    for (int nt = 0; nt < 8; nt++) {
        atomicAdd(pA0 + nt * 8,     acc0[nt][0]);
        atomicAdd(pA0 + nt * 8 + 1, acc0[nt][1]);
        atomicAdd(pB0 + nt * 8,     acc0[nt][2]);
        atomicAdd(pB0 + nt * 8 + 1, acc0[nt][3]);
        atomicAdd(pA1 + nt * 8,     acc1[nt][0]);
        atomicAdd(pA1 + nt * 8 + 1, acc1[nt][1]);
        atomicAdd(pB1 + nt * 8,     acc1[nt][2]);
        atomicAdd(pB1 + nt * 8 + 1, acc1[nt][3]);
    }
}

// ---------------------------------------------------------------------------
// K3: out = x + gelu(seg/max(cnt,1) + x @ root + bias). 8 nodes per block.
// ---------------------------------------------------------------------------
__global__ __launch_bounds__(128) void out_kernel(
    const float* __restrict__ x,
    const float* __restrict__ root,
    const float* __restrict__ bias,
    float* __restrict__ out)
{
    __shared__ float xsh[8][D];
    const int o  = threadIdx.x;
    const int n0 = blockIdx.x * 8;
    const int nmax = (NNODES - n0 < 8) ? (NNODES - n0) : 8;

    for (int t = threadIdx.x; t < 8 * D; t += 128) {
        int r = t >> 7;
        xsh[r][t & 127] = (r < nmax) ? x[(size_t)(n0 + r) * D + (t & 127)] : 0.0f;
    }
    __syncthreads();

    float acc[8];
#pragma unroll
    for (int r = 0; r < 8; r++) acc[r] = 0.0f;

    for (int i = 0; i < D; i++) {
        float w = root[i * D + o];
#pragma unroll
        for (int r = 0; r < 8; r++) acc[r] += xsh[r][i] * w;
    }

    float bb = bias[o];
    for (int r = 0; r < nmax; r++) {
        int n = n0 + r;
        float cnt  = g_cnt[n];
        float aggr = g_seg[(size_t)n * D + o] / fmaxf(cnt, 1.0f);
        float v = aggr + acc[r] + bb;
        float gl = 0.5f * v * (1.0f + erff(v * 0.70710678118654752f));
        out[(size_t)n * D + o] = xsh[r][o] + gl;
    }
}

// ---------------------------------------------------------------------------
// Launch
// ---------------------------------------------------------------------------
extern "C" void kernel_launch(void* const* d_in, const int* in_sizes, int n_in,
                              void* d_out, int out_size)
{
    const float* x    = (const float*)d_in[0];
    const int*   ei   = (const int*)d_in[1];     // int32 (jax downcasts int64)
    const float* ea   = (const float*)d_in[2];
    const float* w1   = (const float*)d_in[3];
    const float* b1   = (const float*)d_in[4];
    const float* w2   = (const float*)d_in[5];
    const float* b2   = (const float*)d_in[6];
    const float* root = (const float*)d_in[7];
    const float* bias = (const float*)d_in[8];
    float*       out  = (float*)d_out;

    zero_kernel<<<(NNODES * D + 255) / 256, 256>>>();
    count_kernel<<<(E_EDGES + 255) / 256, 256>>>(ei);
    pack_kernel<<<W2_PACK_BLOCKS + 8, 256>>>(w2, b2);
    edge_mlp1_kernel<<<E_EDGES / 8, 128>>>(ea, w1, b1);
    bilinear_hmma16_kernel<<<E_EDGES / 128, 256>>>(x, ei);
    out_kernel<<<(NNODES + 7) / 8, 128>>>(x, root, bias, out);
}

// round 14
// speedup vs baseline: 15.4563x; 1.1382x over previous
#include <cuda_runtime.h>
#include <math.h>
#include <stdint.h>

#define E_EDGES 16384
#define NNODES  10000
#define D       128

// Scratch (device globals: no allocation allowed)
__device__ float g_seg[NNODES * D];   // scatter-sum of messages
__device__ float g_cnt[NNODES];       // per-destination edge counts
__device__ uint4 g_w2f4[D * 8 * 8 * 32];   // w2, fp16 paired B-fragments (4 MB)
__device__ uint4 g_b2f4[8 * 8 * 32];       // b2, fp16 paired B-fragments
__device__ uint4 g_w1f4[8 * 8 * 32];       // w1, fp16 paired B-fragments

__device__ __forceinline__ int clamp_node(int v) {
    v = v < 0 ? 0 : v;
    return v >= NNODES ? NNODES - 1 : v;
}

// pack two f32 -> half2 register (lo in low half), single rounding each
__device__ __forceinline__ uint32_t h2f(float lo, float hi) {
    uint32_t r;
    asm("cvt.rn.f16x2.f32 %0, %1, %2;" : "=r"(r) : "f"(hi), "f"(lo));
    return r;
}

// m16n8k16 fp16 mma, fp32 accumulate: D += A * B
__device__ __forceinline__ void mma16(float c[4], uint32_t a0, uint32_t a1,
                                      uint32_t a2, uint32_t a3,
                                      uint32_t b0, uint32_t b1) {
    asm("mma.sync.aligned.m16n8k16.row.col.f32.f16.f16.f32 "
        "{%0,%1,%2,%3}, {%4,%5,%6,%7}, {%8,%9}, {%0,%1,%2,%3};"
        : "+f"(c[0]), "+f"(c[1]), "+f"(c[2]), "+f"(c[3])
        : "r"(a0), "r"(a1), "r"(a2), "r"(a3), "r"(b0), "r"(b1));
}

// ---------------------------------------------------------------------------
// K0: zero accumulators
// ---------------------------------------------------------------------------
__global__ void zero_kernel() {
    int i = blockIdx.x * blockDim.x + threadIdx.x;
    if (i < NNODES * D) g_seg[i] = 0.0f;
    if (i < NNODES)     g_cnt[i] = 0.0f;
}

// ---------------------------------------------------------------------------
// K0b: per-destination edge counts (edge_index is int32)
// ---------------------------------------------------------------------------
__global__ void count_kernel(const int* __restrict__ ei) {
    int e = blockIdx.x * blockDim.x + threadIdx.x;
    if (e < E_EDGES) {
        int d = clamp_node(ei[E_EDGES + e]);
        atomicAdd(&g_cnt[d], 1.0f);
    }
}

// ---------------------------------------------------------------------------
// K1: pack w2, b2, w1 into fp16 paired B-fragment layout (one fused kernel).
// w2 fragment index: ((i*8 + kt)*8 + slot)*32 + lane
//   .x = half2(M[k0][na], M[k0+1][na])   k0 = kt*16 + 2*(lane%4)
//   .y = half2(M[k0+8][na], M[k0+9][na]) na = slot*16 + lane/4
//   .z/.w = same at na + 8
// b2 / w1 are [128][128] row-major matrices (K-dim = row), same pattern.
// ---------------------------------------------------------------------------
#define W2_PACK_BLOCKS (D * 8 * 8 * 32 / 256)   // 1024

__global__ __launch_bounds__(256) void pack_kernel(
    const float* __restrict__ w2, const float* __restrict__ b2,
    const float* __restrict__ w1)
{
    if (blockIdx.x < W2_PACK_BLOCKS) {
        int f = blockIdx.x * 256 + threadIdx.x;       // 0 .. 262143
        int lane = f & 31, slot = (f >> 5) & 7, kt = (f >> 8) & 7, i = f >> 11;
        int c = lane & 3, g = lane >> 2;
        int k0 = kt * 16 + 2 * c;
        int na = slot * 16 + g, nb = na + 8;
        const size_t rs = (size_t)D * D;
        const float* p = w2 + (size_t)k0 * rs + (size_t)i * D;
        uint4 v;
        v.x = h2f(p[na],          p[rs + na]);
        v.y = h2f(p[8 * rs + na], p[9 * rs + na]);
        v.z = h2f(p[nb],          p[rs + nb]);
        v.w = h2f(p[8 * rs + nb], p[9 * rs + nb]);
        g_w2f4[f] = v;
    } else {
        int bb = blockIdx.x - W2_PACK_BLOCKS;         // 0..15
        int f = (bb & 7) * 256 + threadIdx.x;         // 0..2047
        const float* m = (bb < 8) ? b2 : w1;
        int lane = f & 31, slot = (f >> 5) & 7, kt = f >> 8;
        int c = lane & 3, g = lane >> 2;
        int k0 = kt * 16 + 2 * c;
        int na = slot * 16 + g, nb = na + 8;
        const float* p = m + (size_t)k0 * D;
        uint4 v;
        v.x = h2f(p[na],         p[D + na]);
        v.y = h2f(p[8 * D + na], p[9 * D + na]);
        v.z = h2f(p[nb],         p[D + nb]);
        v.w = h2f(p[8 * D + nb], p[9 * D + nb]);
        if (bb < 8) g_b2f4[f] = v; else g_w1f4[f] = v;
    }
}

// ---------------------------------------------------------------------------
// K2: fully fused NNConv message kernel (fp16 m16n8k16 HMMA).
// Phase 1 (in-register): h = relu(ea @ w1 + b1) via MMA — the D-fragment
//   layout of this GEMM is exactly the A-fragment layout the main loop needs.
// Phase 2: msg[e,o] = sum_i x[src,i] * (sum_k h[e,k] w2[k][i*128+o] + b2[..])
// Block = 128 edges (single wave: 128 blocks). 8 warps = 4 mg x 2 ng.
// Warp: 32 edges (2 m-frags) x 64 outs. fp32 accumulate throughout.
// ---------------------------------------------------------------------------
__global__ __launch_bounds__(256, 1) void bilinear_fused_kernel(
    const float* __restrict__ x, const int* __restrict__ ei,
    const float* __restrict__ ea, const float* __restrict__ b1)
{
    const int lane = threadIdx.x & 31, wid = threadIdx.x >> 5;
    const int mg = wid >> 1, ng = wid & 1;
    const int e0 = blockIdx.x * 128 + mg * 32;
    const int g  = lane >> 2, c = lane & 3;

    // ---- Phase 1: h fragments via MMA (each ng-warp redundantly computes
    //      h for its 32 edges; 512 MMAs vs 4096 in phase 2) ----
    float h0[16][4], h1[16][4];
#pragma unroll
    for (int nt = 0; nt < 16; nt++)
#pragma unroll
        for (int j = 0; j < 4; j++) { h0[nt][j] = 0.0f; h1[nt][j] = 0.0f; }
    {
        const float* eA0 = ea + (size_t)(e0 + g) * D;
        const float* eB0 = ea + (size_t)(e0 + g + 8) * D;
        const float* eA1 = ea + (size_t)(e0 + 16 + g) * D;
        const float* eB1 = ea + (size_t)(e0 + 16 + g + 8) * D;
#pragma unroll
        for (int kt = 0; kt < 8; kt++) {
            int b = kt * 16 + 2 * c;
            const uint32_t a00 = h2f(eA0[b],     eA0[b + 1]);
            const uint32_t a01 = h2f(eB0[b],     eB0[b + 1]);
            const uint32_t a02 = h2f(eA0[b + 8], eA0[b + 9]);
            const uint32_t a03 = h2f(eB0[b + 8], eB0[b + 9]);
            const uint32_t a10 = h2f(eA1[b],     eA1[b + 1]);
            const uint32_t a11 = h2f(eB1[b],     eB1[b + 1]);
            const uint32_t a12 = h2f(eA1[b + 8], eA1[b + 9]);
            const uint32_t a13 = h2f(eB1[b + 8], eB1[b + 9]);
            const uint4* wk = g_w1f4 + (size_t)(kt * 8) * 32 + lane;
#pragma unroll
            for (int slot = 0; slot < 8; slot++) {
                uint4 w = __ldg(wk + slot * 32);
                mma16(h0[2 * slot],     a00, a01, a02, a03, w.x, w.y);
                mma16(h0[2 * slot + 1], a00, a01, a02, a03, w.z, w.w);
                mma16(h1[2 * slot],     a10, a11, a12, a13, w.x, w.y);
                mma16(h1[2 * slot + 1], a10, a11, a12, a13, w.z, w.w);
            }
        }
        // bias + relu in registers (cols 2c, 2c+1 per n-tile)
#pragma unroll
        for (int nt = 0; nt < 16; nt++) {
            float2 bb = *(const float2*)(b1 + nt * 8 + 2 * c);
            h0[nt][0] = fmaxf(h0[nt][0] + bb.x, 0.0f);
            h0[nt][1] = fmaxf(h0[nt][1] + bb.y, 0.0f);
            h0[nt][2] = fmaxf(h0[nt][2] + bb.x, 0.0f);
            h0[nt][3] = fmaxf(h0[nt][3] + bb.y, 0.0f);
            h1[nt][0] = fmaxf(h1[nt][0] + bb.x, 0.0f);
            h1[nt][1] = fmaxf(h1[nt][1] + bb.y, 0.0f);
            h1[nt][2] = fmaxf(h1[nt][2] + bb.x, 0.0f);
            h1[nt][3] = fmaxf(h1[nt][3] + bb.y, 0.0f);
        }
    }

    // ---- Phase 2: main bilinear loop ----
    const int sA0 = clamp_node(ei[e0 + g]);
    const int sB0 = clamp_node(ei[e0 + g + 8]);
    const int sA1 = clamp_node(ei[e0 + 16 + g]);
    const int sB1 = clamp_node(ei[e0 + 16 + g + 8]);
    const float* xA0 = x + (size_t)sA0 * D;
    const float* xB0 = x + (size_t)sB0 * D;
    const float* xA1 = x + (size_t)sA1 * D;
    const float* xB1 = x + (size_t)sB1 * D;

    float acc0[8][4], acc1[8][4];
#pragma unroll
    for (int nt = 0; nt < 8; nt++)
#pragma unroll
        for (int j = 0; j < 4; j++) { acc0[nt][j] = 0.0f; acc1[nt][j] = 0.0f; }

    for (int i = 0; i < D; i++) {
        const float x0g = __ldg(xA0 + i), x0h = __ldg(xB0 + i);
        const float x1g = __ldg(xA1 + i), x1h = __ldg(xB1 + i);
        const uint4* wf = g_w2f4 + ((size_t)(i * 8) * 8 + ng * 4) * 32 + lane;
#pragma unroll
        for (int kt = 0; kt < 8; kt++) {
            const uint32_t a00 = h2f(h0[2 * kt][0] * x0g,     h0[2 * kt][1] * x0g);
            const uint32_t a01 = h2f(h0[2 * kt][2] * x0h,     h0[2 * kt][3] * x0h);
            const uint32_t a02 = h2f(h0[2 * kt + 1][0] * x0g, h0[2 * kt + 1][1] * x0g);
            const uint32_t a03 = h2f(h0[2 * kt + 1][2] * x0h, h0[2 * kt + 1][3] * x0h);
            const uint32_t a10 = h2f(h1[2 * kt][0] * x1g,     h1[2 * kt][1] * x1g);
            const uint32_t a11 = h2f(h1[2 * kt][2] * x1h,     h1[2 * kt][3] * x1h);
            const uint32_t a12 = h2f(h1[2 * kt + 1][0] * x1g, h1[2 * kt + 1][1] * x1g);
            const uint32_t a13 = h2f(h1[2 * kt + 1][2] * x1h, h1[2 * kt + 1][3] * x1h);
            const uint4* wk = wf + (size_t)kt * 8 * 32;
#pragma unroll
            for (int ntp = 0; ntp < 4; ntp++) {
                uint4 b = __ldg(wk + ntp * 32);
                mma16(acc0[2 * ntp],     a00, a01, a02, a03, b.x, b.y);
                mma16(acc0[2 * ntp + 1], a00, a01, a02, a03, b.z, b.w);
                mma16(acc1[2 * ntp],     a10, a11, a12, a13, b.x, b.y);
                mma16(acc1[2 * ntp + 1], a10, a11, a12, a13, b.z, b.w);
            }
        }
    }

    // b2 term: A = gathered x rows (fp32 -> single rounding to fp16)
    {
        const uint4* bf = g_b2f4 + (size_t)(ng * 4) * 32 + lane;
#pragma unroll
        for (int kt = 0; kt < 8; kt++) {
            int b = kt * 16 + 2 * c;
            const uint32_t a00 = h2f(xA0[b],     xA0[b + 1]);
            const uint32_t a01 = h2f(xB0[b],     xB0[b + 1]);
            const uint32_t a02 = h2f(xA0[b + 8], xA0[b + 9]);
            const uint32_t a03 = h2f(xB0[b + 8], xB0[b + 9]);
            const uint32_t a10 = h2f(xA1[b],     xA1[b + 1]);
            const uint32_t a11 = h2f(xB1[b],     xB1[b + 1]);
            const uint32_t a12 = h2f(xA1[b + 8], xA1[b + 9]);
            const uint32_t a13 = h2f(xB1[b + 8], xB1[b + 9]);
            const uint4* bk = bf + (size_t)kt * 8 * 32;
#pragma unroll
            for (int ntp = 0; ntp < 4; ntp++) {
                uint4 b2v = __ldg(bk + ntp * 32);
                mma16(acc0[2 * ntp],     a00, a01, a02, a03, b2v.x, b2v.y);
                mma16(acc0[2 * ntp + 1], a00, a01, a02, a03, b2v.z, b2v.w);
                mma16(acc1[2 * ntp],     a10, a11, a12, a13, b2v.x, b2v.y);
                mma16(acc1[2 * ntp + 1], a10, a11, a12, a13, b2v.z, b2v.w);
            }
        }
    }

    // Epilogue: D frag rows g/g+8, cols 2c/2c+1
    const int dA0 = clamp_node(ei[E_EDGES + e0 + g]);
    const int dB0 = clamp_node(ei[E_EDGES + e0 + g + 8]);
    const int dA1 = clamp_node(ei[E_EDGES + e0 + 16 + g]);
    const int dB1 = clamp_node(ei[E_EDGES + e0 + 16 + g + 8]);
    float* pA0 = g_seg + (size_t)dA0 * D + ng * 64 + 2 * c;
    float* pB0 = g_seg + (size_t)dB0 * D + ng * 64 + 2 * c;
    float* pA1 = g_seg + (size_t)dA1 * D + ng * 64 + 2 * c;
    float* pB1 = g_seg + (size_t)dB1 * D + ng * 64 + 2 * c;
#pragma unroll
    for (int nt = 0; nt < 8; nt++) {
        atomicAdd(pA0 + nt * 8,     acc0[nt][0]);
        atomicAdd(pA0 + nt * 8 + 1, acc0[nt][1]);
        atomicAdd(pB0 + nt * 8,     acc0[nt][2]);
        atomicAdd(pB0 + nt * 8 + 1, acc0[nt][3]);
        atomicAdd(pA1 + nt * 8,     acc1[nt][0]);
        atomicAdd(pA1 + nt * 8 + 1, acc1[nt][1]);
        atomicAdd(pB1 + nt * 8,     acc1[nt][2]);
        atomicAdd(pB1 + nt * 8 + 1, acc1[nt][3]);
    }
}

// ---------------------------------------------------------------------------
// K3: out = x + gelu(seg/max(cnt,1) + x @ root + bias). 16 nodes per block.
// ---------------------------------------------------------------------------
__global__ __launch_bounds__(128) void out_kernel(
    const float* __restrict__ x,
    const float* __restrict__ root,
    const float* __restrict__ bias,
    float* __restrict__ out)
{
    __shared__ float xsh[16][D];
    const int o  = threadIdx.x;
    const int n0 = blockIdx.x * 16;
    const int nmax = (NNODES - n0 < 16) ? (NNODES - n0) : 16;

    for (int t = threadIdx.x; t < 16 * D; t += 128) {
        int r = t >> 7;
        xsh[r][t & 127] = (r < nmax) ? x[(size_t)(n0 + r) * D + (t & 127)] : 0.0f;
    }
    __syncthreads();

    float acc[16];
#pragma unroll
    for (int r = 0; r < 16; r++) acc[r] = 0.0f;

    for (int i = 0; i < D; i++) {
        float w = root[i * D + o];
#pragma unroll
        for (int r = 0; r < 16; r++) acc[r] += xsh[r][i] * w;
    }

    float bb = bias[o];
    for (int r = 0; r < nmax; r++) {
        int n = n0 + r;
        float cnt  = g_cnt[n];
        float aggr = g_seg[(size_t)n * D + o] / fmaxf(cnt, 1.0f);
        float v = aggr + acc[r] + bb;
        float gl = 0.5f * v * (1.0f + erff(v * 0.70710678118654752f));
        out[(size_t)n * D + o] = xsh[r][o] + gl;
    }
}

// ---------------------------------------------------------------------------
// Launch
// ---------------------------------------------------------------------------
extern "C" void kernel_launch(void* const* d_in, const int* in_sizes, int n_in,
                              void* d_out, int out_size)
{
    const float* x    = (const float*)d_in[0];
    const int*   ei   = (const int*)d_in[1];     // int32 (jax downcasts int64)
    const float* ea   = (const float*)d_in[2];
    const float* w1   = (const float*)d_in[3];
    const float* b1   = (const float*)d_in[4];
    const float* w2   = (const float*)d_in[5];
    const float* b2   = (const float*)d_in[6];
    const float* root = (const float*)d_in[7];
    const float* bias = (const float*)d_in[8];
    float*       out  = (float*)d_out;

    zero_kernel<<<(NNODES * D + 255) / 256, 256>>>();
    count_kernel<<<(E_EDGES + 255) / 256, 256>>>(ei);
    pack_kernel<<<W2_PACK_BLOCKS + 16, 256>>>(w2, b2, w1);
    bilinear_fused_kernel<<<E_EDGES / 128, 256>>>(x, ei, ea, b1);
    out_kernel<<<(NNODES + 15) / 16, 128>>>(x, root, bias, out);
}